// round 16
// baseline (speedup 1.0000x reference)
#include <cuda_runtime.h>
#include <cuda_bf16.h>
#include <math.h>
#include <stdint.h>

// Problem constants (fixed by the dataset)
#define BATCH   512
#define IN_DIM  128
#define OUT_DIM 128
#define NFEAT   9                   // silu + 8 basis functions
#define BM      16                  // batch rows per block (= one m16 tile)
#define BO      32                  // out cols per block (4 n8 tiles)
#define MT      (BATCH / BM)        // 32 m-tiles
#define OT      (OUT_DIM / BO)      // 4 o-tiles
#define CHI     16                  // input dims per smem chunk
#define NCH     (IN_DIM / CHI)      // 8 chunks (full K per block!)
#define KCC     12                  // k16 chunks per smem chunk (16*12/16)
#define NTHR    512
#define TSTR    200                 // smem row stride in bf16 (192 cols + 8 pad)
#define A_ELE   (BM * TSTR)         // 3200
#define B_ELE   (BO * TSTR)         // 6400
#define BUF_ELE (2 * A_ELE + 2 * B_ELE)          // 19200 bf16 per buffer
#define SMEM_BYTES (2 * BUF_ELE * 2)             // 76800 bytes (2 buffers)

// ---------------------------------------------------------------------------
// HMMA m16n8k16 bf16 -> f32 (generic PTX, sm_80+; legal on sm_103 target)
// ---------------------------------------------------------------------------
__device__ __forceinline__ void mma_bf16(float* c, const uint32_t* a,
                                         const uint32_t* b) {
    asm volatile(
        "mma.sync.aligned.m16n8k16.row.col.f32.bf16.bf16.f32 "
        "{%0,%1,%2,%3}, {%4,%5,%6,%7}, {%8,%9}, {%0,%1,%2,%3};\n"
        : "+f"(c[0]), "+f"(c[1]), "+f"(c[2]), "+f"(c[3])
        : "r"(a[0]), "r"(a[1]), "r"(a[2]), "r"(a[3]),
          "r"(b[0]), "r"(b[1]));
}

__device__ __forceinline__ uint32_t pack_hl(float a, float b) {
    __nv_bfloat162 p = __floats2bfloat162_rn(a, b);
    return *(uint32_t*)&p;
}

// Prefetched inputs for one chunk
struct Pref {
    float  xv;           // valid for t < 256
    float4 c0, c1;
    float  mk, fsb, fss;
};

// ---------------------------------------------------------------------------
// Single kernel, 512 threads, 128 blocks = (32 m-tiles x 4 o-tiles).
// Full K per block in 8 double-buffered smem chunks; register accumulation;
// fixed-order cross-warp sum -> direct out write.
// NO split-K, NO partials, NO grid barrier, NO reduce pass.
// ---------------------------------------------------------------------------
__global__ void __launch_bounds__(NTHR, 1)
fused_kernel(const float* __restrict__ x,
             const float* __restrict__ grid,
             const float* __restrict__ coef,
             const float* __restrict__ sb,
             const float* __restrict__ ss,
             const float* __restrict__ mask,
             float* __restrict__ out) {
    extern __shared__ __nv_bfloat16 sm[];

    const int t    = threadIdx.x;
    const int warp = t >> 5;
    const int lane = t & 31;
    const int m0   = blockIdx.x * BM;
    const int o0   = blockIdx.y * BO;

    // ---- uniform extended knot vector (division-free) ----
    const float g0 = grid[0];
    const float g5 = grid[5];
    const float step = (g5 - g0) * 0.2f;
    const float inv1 = __frcp_rn(step);
    const float invr[3] = { inv1, 0.5f * inv1, inv1 * (1.0f / 3.0f) };

    float tk[12];
    tk[0]  = g0 - step * 3.0f;
    tk[1]  = g0 - step * 2.0f;
    tk[2]  = g0 - step;
    tk[3]  = g0;
    tk[4]  = grid[1];
    tk[5]  = grid[2];
    tk[6]  = grid[3];
    tk[7]  = grid[4];
    tk[8]  = g5;
    tk[9]  = g5 + step;
    tk[10] = g5 + step * 2.0f;
    tk[11] = g5 + step * 3.0f;

    // ---- chunk input loader (registers only) ----
    auto load_chunk = [&](int c, Pref& p) {
        const int i0c = c * CHI;
        if (t < 256)
            p.xv = __ldg(&x[(m0 + (t >> 4)) * IN_DIM + i0c + (t & 15)]);
        const int o = t >> 4;           // 0..31
        const int i = t & 15;
        const int s = (o0 + o) * IN_DIM + i0c + i;
        p.c0  = __ldg((const float4*)&coef[s * 8]);
        p.c1  = __ldg((const float4*)&coef[s * 8 + 4]);
        p.mk  = __ldg(&mask[s]);
        p.fsb = __ldg(&sb[s]);
        p.fss = __ldg(&ss[s]);
    };

    // ---- chunk tile builder (regs -> smem buffer) ----
    auto build_chunk = [&](const Pref& p, __nv_bfloat16* buf) {
        __nv_bfloat16* Ah = buf;
        __nv_bfloat16* Al = buf + A_ELE;
        __nv_bfloat16* Bh = buf + 2 * A_ELE;
        __nv_bfloat16* Bl = buf + 2 * A_ELE + B_ELE;

        if (t < 256) {                  // A: 16 n x 16 i
            const int n = t >> 4;
            const int i = t & 15;
            const float xv = p.xv;

            const float sig = __frcp_rn(1.0f + __expf(-xv));
            float f[NFEAT];
            f[0] = xv * sig;            // silu

            float B[11];
#pragma unroll
            for (int m = 0; m < 11; m++)
                B[m] = (xv >= tk[m] && xv < tk[m + 1]) ? 1.0f : 0.0f;
#pragma unroll
            for (int r = 1; r <= 3; r++) {
                const float iv = invr[r - 1];
#pragma unroll
                for (int m = 0; m < 11 - r; m++) {
                    float alpha = (xv - tk[m]) * iv;
                    float beta  = (tk[m + r + 1] - xv) * iv;
                    B[m] = alpha * B[m] + beta * B[m + 1];
                }
            }
#pragma unroll
            for (int j = 0; j < 8; j++) f[1 + j] = B[j];

            uint32_t* ph = (uint32_t*)&Ah[n * TSTR + i * 12];
            uint32_t* pl = (uint32_t*)&Al[n * TSTR + i * 12];
#pragma unroll
            for (int jp = 0; jp < 4; jp++) {
                const float h0 = __bfloat162float(__float2bfloat16(f[jp * 2]));
                const float h1 = __bfloat162float(__float2bfloat16(f[jp * 2 + 1]));
                ph[jp] = pack_hl(h0, h1);
                pl[jp] = pack_hl(f[jp * 2] - h0, f[jp * 2 + 1] - h1);
            }
            const float h8 = __bfloat162float(__float2bfloat16(f[8]));
            ph[4] = pack_hl(h8, 0.f);
            pl[4] = pack_hl(f[8] - h8, 0.f);
            ph[5] = 0u;
            pl[5] = 0u;
        }

        {                               // B: 32 o x 16 i
            const int o = t >> 4;
            const int i = t & 15;
            float w[NFEAT];
            w[0] = p.mk * p.fsb;
            const float wsc = p.mk * p.fss;
            w[1] = wsc * p.c0.x; w[2] = wsc * p.c0.y;
            w[3] = wsc * p.c0.z; w[4] = wsc * p.c0.w;
            w[5] = wsc * p.c1.x; w[6] = wsc * p.c1.y;
            w[7] = wsc * p.c1.z; w[8] = wsc * p.c1.w;

            uint32_t* ph = (uint32_t*)&Bh[o * TSTR + i * 12];
            uint32_t* pl = (uint32_t*)&Bl[o * TSTR + i * 12];
#pragma unroll
            for (int jp = 0; jp < 4; jp++) {
                const float h0 = __bfloat162float(__float2bfloat16(w[jp * 2]));
                const float h1 = __bfloat162float(__float2bfloat16(w[jp * 2 + 1]));
                ph[jp] = pack_hl(h0, h1);
                pl[jp] = pack_hl(w[jp * 2] - h0, w[jp * 2 + 1] - h1);
            }
            const float h8 = __bfloat162float(__float2bfloat16(w[8]));
            ph[4] = pack_hl(h8, 0.f);
            pl[4] = pack_hl(w[8] - h8, 0.f);
            ph[5] = 0u;
            pl[5] = 0u;
        }
    };

    // ---- MMA warp mapping: warp = wn*4 + wk ----
    const int wk = warp & 3;            // kc-quarter within each chunk
    const int wn = warp >> 2;           // n8 tile (8 o-cols)
    const int qr = lane >> 2;
    const int qc = (lane & 3) * 2;

    float acc[4] = {0.f, 0.f, 0.f, 0.f};

    auto mma_chunk = [&](const __nv_bfloat16* buf) {
        const __nv_bfloat16* Ah = buf;
        const __nv_bfloat16* Al = buf + A_ELE;
        const __nv_bfloat16* Bh = buf + 2 * A_ELE;
        const __nv_bfloat16* Bl = buf + 2 * A_ELE + B_ELE;
#pragma unroll
        for (int j = 0; j < KCC / 4; j++) {   // 3 kc per warp per chunk
            const int kc = wk * (KCC / 4) + j;
            uint32_t ah[4], al[4];
            const int r0 = qr * TSTR + kc * 16 + qc;
            const int r8 = r0 + 8 * TSTR;
            ah[0] = *(const uint32_t*)&Ah[r0];
            ah[1] = *(const uint32_t*)&Ah[r8];
            ah[2] = *(const uint32_t*)&Ah[r0 + 8];
            ah[3] = *(const uint32_t*)&Ah[r8 + 8];
            al[0] = *(const uint32_t*)&Al[r0];
            al[1] = *(const uint32_t*)&Al[r8];
            al[2] = *(const uint32_t*)&Al[r0 + 8];
            al[3] = *(const uint32_t*)&Al[r8 + 8];

            const int b0 = (wn * 8 + qr) * TSTR + kc * 16 + qc;
            uint32_t bh[2], bl[2];
            bh[0] = *(const uint32_t*)&Bh[b0];
            bh[1] = *(const uint32_t*)&Bh[b0 + 8];
            bl[0] = *(const uint32_t*)&Bl[b0];
            bl[1] = *(const uint32_t*)&Bl[b0 + 8];

            mma_bf16(acc, ah, bh);   // Ah*Bh
            mma_bf16(acc, ah, bl);   // Ah*Bl
            mma_bf16(acc, al, bh);   // Al*Bh
        }
    };

    // ---- prologue: chunk 0 ----
    {
        Pref p;
        load_chunk(0, p);
        build_chunk(p, sm);             // buffer 0
    }
    __syncthreads();

    // ---- main loop: MMA chunk c, build chunk c+1 into the other buffer ----
#pragma unroll 1
    for (int c = 0; c < NCH; c++) {
        Pref p;
        if (c < NCH - 1) load_chunk(c + 1, p);       // LDGs fly over MMA
        mma_chunk(sm + (c & 1) * BUF_ELE);
        if (c < NCH - 1) build_chunk(p, sm + ((c + 1) & 1) * BUF_ELE);
        __syncthreads();
    }

    // ---- fixed-order cross-warp k-reduction (deterministic) + store ----
    float4* stg = (float4*)sm;          // reuse smem (all MMA reads done)
    stg[warp * 32 + lane] = make_float4(acc[0], acc[1], acc[2], acc[3]);
    __syncthreads();

    if (warp < 4) {                     // warp handles nt = warp
        const int nt = warp;
        float4 s = stg[(nt * 4 + 0) * 32 + lane];
        const float4 s1 = stg[(nt * 4 + 1) * 32 + lane];
        const float4 s2 = stg[(nt * 4 + 2) * 32 + lane];
        const float4 s3 = stg[(nt * 4 + 3) * 32 + lane];
        s.x += s1.x; s.y += s1.y; s.z += s1.z; s.w += s1.w;
        s.x += s2.x; s.y += s2.y; s.z += s2.z; s.w += s2.w;
        s.x += s3.x; s.y += s3.y; s.z += s3.z; s.w += s3.w;

        const int row = m0 + qr;
        const int col = o0 + nt * 8 + qc;
        *(float2*)&out[row * OUT_DIM + col]       = make_float2(s.x, s.y);
        *(float2*)&out[(row + 8) * OUT_DIM + col] = make_float2(s.z, s.w);
    }
}

// ---------------------------------------------------------------------------
extern "C" void kernel_launch(void* const* d_in, const int* in_sizes, int n_in,
                              void* d_out, int out_size) {
    const float* x    = (const float*)d_in[0];
    const float* grid = (const float*)d_in[1];
    const float* coef = (const float*)d_in[2];
    const float* sb   = (const float*)d_in[3];
    const float* ss   = (const float*)d_in[4];
    const float* mask = (const float*)d_in[5];
    float* out = (float*)d_out;

    cudaFuncSetAttribute(fused_kernel,
                         cudaFuncAttributeMaxDynamicSharedMemorySize,
                         SMEM_BYTES);
    fused_kernel<<<dim3(MT, OT), NTHR, SMEM_BYTES>>>(
        x, grid, coef, sb, ss, mask, out);
}

// round 17
// speedup vs baseline: 1.1750x; 1.1750x over previous
#include <cuda_runtime.h>
#include <cuda_bf16.h>
#include <math.h>
#include <stdint.h>

// Problem constants (fixed by the dataset)
#define BATCH   512
#define IN_DIM  128
#define OUT_DIM 128
#define NFEAT   9                   // silu + 8 basis functions
#define IPB     8                   // input dims per block (k-split)
#define KPAD    80                  // 8 i * 9 cols = 72, padded to 5 x k16
#define NKC     (KPAD / 16)         // 5 k-chunks
#define SPLITS  (IN_DIM / IPB)      // 16 k-splits
#define BM      64                  // batch rows per block
#define MT      (BATCH / BM)        // 8 m-tiles
#define NBLK    (MT * SPLITS)       // 128 blocks (single wave on 148 SMs)
#define NTHR    512
#define NOUT    (BATCH * OUT_DIM)   // 65536
#define TSTR    88                  // smem row stride in bf16 (176B, conflict-free)
#define SMEM_BYTES ((2 * BM * TSTR + 2 * OUT_DIM * TSTR) * 2)  // 67584

// Scratch (device globals — no allocation in kernel_launch)
__device__ float        g_P[SPLITS * NOUT];  // split-K partials (4.2 MB)
__device__ unsigned int g_bar;               // monotonic barrier ticket counter

// ---------------------------------------------------------------------------
// HMMA m16n8k16 bf16 -> f32 (generic PTX, sm_80+; legal on sm_103 target)
// ---------------------------------------------------------------------------
__device__ __forceinline__ void mma_bf16(float* c, const uint32_t* a,
                                         const uint32_t* b) {
    asm volatile(
        "mma.sync.aligned.m16n8k16.row.col.f32.bf16.bf16.f32 "
        "{%0,%1,%2,%3}, {%4,%5,%6,%7}, {%8,%9}, {%0,%1,%2,%3};\n"
        : "+f"(c[0]), "+f"(c[1]), "+f"(c[2]), "+f"(c[3])
        : "r"(a[0]), "r"(a[1]), "r"(a[2]), "r"(a[3]),
          "r"(b[0]), "r"(b[1]));
}

// ---------------------------------------------------------------------------
// Single kernel, 512 threads, 128 blocks = (8 m-tiles x 16 k-splits):
//   phase 1: build bf16 hi/lo tiles in smem (closed-form 4-tap B-spline,
//            9-col packing, 5 k16-chunks), HMMA GEMM
//            (D = Ah*Bh + Ah*Bl + Al*Bh) -> split-K partials
//   global ticket barrier (replay-safe)
//   phase 2: reduce L2-warm partials, 1 output per thread
// ---------------------------------------------------------------------------
__global__ void __launch_bounds__(NTHR, 1)
fused_kernel(const float* __restrict__ x,
             const float* __restrict__ grid,
             const float* __restrict__ coef,
             const float* __restrict__ sb,
             const float* __restrict__ ss,
             const float* __restrict__ mask,
             float* __restrict__ out) {
    extern __shared__ __nv_bfloat16 sm[];
    __nv_bfloat16* Ah = sm;                          // [BM][TSTR]
    __nv_bfloat16* Al = sm + BM * TSTR;
    __nv_bfloat16* Bh = sm + 2 * BM * TSTR;          // [OUT_DIM][TSTR]
    __nv_bfloat16* Bl = sm + 2 * BM * TSTR + OUT_DIM * TSTR;
    __shared__ unsigned int s_target;

    const int t    = threadIdx.x;
    const int warp = t >> 5;
    const int lane = t & 31;
    const int m0   = blockIdx.x * BM;
    const int i0   = blockIdx.y * IPB;

    // ---- uniform knots: only g0/g5 needed for the closed form ----
    const float g0 = grid[0];
    const float g5 = grid[5];
    const float step = (g5 - g0) * 0.2f;
    const float inv1 = __frcp_rn(step);
    const float tk0  = g0 - step * 3.0f;     // extended-knot origin

    // ---- A build: 64 n x 8 i = 512 x-values, 1 per thread ----
    {
        const int n  = t >> 3;
        const int i  = t & 7;
        const float xv = __ldg(&x[(m0 + n) * IN_DIM + i0 + i]);

        const float sig = __frcp_rn(1.0f + __expf(-xv));
        float f[NFEAT];
        f[0] = xv * sig;                      // silu

        // closed-form cubic B-spline: cell c, local coord u, 4 taps
        const float s  = (xv - tk0) * inv1;
        const float cf = floorf(s);
        const int   c  = (int)cf;
        const float u  = s - cf;
        const float u2 = u * u;
        const float u3 = u2 * u;
        const float om = 1.0f - u;
        const float v0 = om * om * om * (1.0f / 6.0f);
        const float v1 = (3.0f * u3 - 6.0f * u2 + 4.0f) * (1.0f / 6.0f);
        const float v2 = (-3.0f * u3 + 3.0f * u2 + 3.0f * u + 1.0f) * (1.0f / 6.0f);
        const float v3 = u3 * (1.0f / 6.0f);

#pragma unroll
        for (int j = 0; j < 8; j++) {
            const int d = c - j;
            f[1 + j] = (d == 3) ? v0 : (d == 2) ? v1
                     : (d == 1) ? v2 : (d == 0) ? v3 : 0.0f;
        }

        const int base = n * TSTR + i * NFEAT;
#pragma unroll
        for (int j = 0; j < NFEAT; j++) {
            const __nv_bfloat16 h = __float2bfloat16(f[j]);
            Ah[base + j] = h;
            Al[base + j] = __float2bfloat16(f[j] - __bfloat162float(h));
        }
        if (i == 0) {                       // zero pad cols 72..79 of row n
            uint32_t* zh = (uint32_t*)&Ah[n * TSTR + 72];
            uint32_t* zl = (uint32_t*)&Al[n * TSTR + 72];
#pragma unroll
            for (int q = 0; q < 4; q++) { zh[q] = 0u; zl[q] = 0u; }
        }
    }

    // ---- B build: 128 o x 8 i = 1024 (o,i) pairs, 2 per thread ----
#pragma unroll
    for (int q = 0; q < 2; q++) {
        const int p = t + NTHR * q;
        const int o = p >> 3;
        const int i = p & 7;
        const int s = o * IN_DIM + i0 + i;

        const float4 c0 = __ldg((const float4*)&coef[s * 8]);
        const float4 c1 = __ldg((const float4*)&coef[s * 8 + 4]);
        const float mk  = __ldg(&mask[s]);
        const float wsc = mk * __ldg(&ss[s]);

        float w[NFEAT];
        w[0] = mk * __ldg(&sb[s]);
        w[1] = wsc * c0.x; w[2] = wsc * c0.y; w[3] = wsc * c0.z; w[4] = wsc * c0.w;
        w[5] = wsc * c1.x; w[6] = wsc * c1.y; w[7] = wsc * c1.z; w[8] = wsc * c1.w;

        const int base = o * TSTR + i * NFEAT;
#pragma unroll
        for (int j = 0; j < NFEAT; j++) {
            const __nv_bfloat16 h = __float2bfloat16(w[j]);
            Bh[base + j] = h;
            Bl[base + j] = __float2bfloat16(w[j] - __bfloat162float(h));
        }
        if (i == 0) {                       // zero pad cols 72..79 of row o
            uint32_t* zh = (uint32_t*)&Bh[o * TSTR + 72];
            uint32_t* zl = (uint32_t*)&Bl[o * TSTR + 72];
#pragma unroll
            for (int z = 0; z < 4; z++) { zh[z] = 0u; zl[z] = 0u; }
        }
    }

    __syncthreads();

    // ---- HMMA GEMM ----
    // warp = (wm 0..3, wn 0..3): rows wm*16..+16, cols wn*32..+32 (4 n8 tiles)
    const int wm = warp & 3;
    const int wn = warp >> 2;
    const int qr = lane >> 2;
    const int qc = (lane & 3) * 2;

    float acc[4][4];
#pragma unroll
    for (int a = 0; a < 4; a++)
#pragma unroll
        for (int b = 0; b < 4; b++) acc[a][b] = 0.f;

#pragma unroll
    for (int kc = 0; kc < NKC; kc++) {
        uint32_t ah[4], al[4];
        {
            const int r0 = (wm * 16 + qr) * TSTR + kc * 16 + qc;
            const int r8 = r0 + 8 * TSTR;
            ah[0] = *(const uint32_t*)&Ah[r0];
            ah[1] = *(const uint32_t*)&Ah[r8];
            ah[2] = *(const uint32_t*)&Ah[r0 + 8];
            ah[3] = *(const uint32_t*)&Ah[r8 + 8];
            al[0] = *(const uint32_t*)&Al[r0];
            al[1] = *(const uint32_t*)&Al[r8];
            al[2] = *(const uint32_t*)&Al[r0 + 8];
            al[3] = *(const uint32_t*)&Al[r8 + 8];
        }
#pragma unroll
        for (int nt = 0; nt < 4; nt++) {
            const int b0 = (wn * 32 + nt * 8 + qr) * TSTR + kc * 16 + qc;
            uint32_t bh[2], bl[2];
            bh[0] = *(const uint32_t*)&Bh[b0];
            bh[1] = *(const uint32_t*)&Bh[b0 + 8];
            bl[0] = *(const uint32_t*)&Bl[b0];
            bl[1] = *(const uint32_t*)&Bl[b0 + 8];

            mma_bf16(acc[nt], ah, bh);   // Ah*Bh
            mma_bf16(acc[nt], ah, bl);   // Ah*Bl
            mma_bf16(acc[nt], al, bh);   // Al*Bh
        }
    }

    // ---- store partials ----
    {
        float* P = &g_P[blockIdx.y * NOUT];
#pragma unroll
        for (int nt = 0; nt < 4; nt++) {
            const int row = m0 + wm * 16 + qr;
            const int col = wn * 32 + nt * 8 + qc;
            *(float2*)&P[row * OUT_DIM + col]       = make_float2(acc[nt][0], acc[nt][1]);
            *(float2*)&P[(row + 8) * OUT_DIM + col] = make_float2(acc[nt][2], acc[nt][3]);
        }
    }

    // ---- grid barrier (monotonic ticket; works across graph replays) ----
    __threadfence();
    __syncthreads();
    if (t == 0) {
        unsigned int ticket = atomicAdd(&g_bar, 1u);
        s_target = ticket - (ticket & (NBLK - 1)) + NBLK;  // epoch base + 128
    }
    __syncthreads();
    if (t == 0) {
        const unsigned int target = s_target;
        while (*(volatile unsigned int*)&g_bar < target) { }
    }
    __syncthreads();
    __threadfence();

    // ---- phase 2: reduce L2-warm partials, 1 output per thread ----
    {
        const int flat = blockIdx.y * MT + blockIdx.x;   // 0..127
        const int idx  = flat * NTHR + t;                // 0..65535
        float v[SPLITS];
#pragma unroll
        for (int q = 0; q < SPLITS; q++)
            v[q] = g_P[q * NOUT + idx];
        float s = 0.0f;
#pragma unroll
        for (int q = 0; q < SPLITS; q++)
            s += v[q];
        out[idx] = s;
    }
}

// ---------------------------------------------------------------------------
extern "C" void kernel_launch(void* const* d_in, const int* in_sizes, int n_in,
                              void* d_out, int out_size) {
    const float* x    = (const float*)d_in[0];
    const float* grid = (const float*)d_in[1];
    const float* coef = (const float*)d_in[2];
    const float* sb   = (const float*)d_in[3];
    const float* ss   = (const float*)d_in[4];
    const float* mask = (const float*)d_in[5];
    float* out = (float*)d_out;

    cudaFuncSetAttribute(fused_kernel,
                         cudaFuncAttributeMaxDynamicSharedMemorySize,
                         SMEM_BYTES);
    fused_kernel<<<dim3(MT, SPLITS), NTHR, SMEM_BYTES>>>(
        x, grid, coef, sb, ss, mask, out);
}